// round 1
// baseline (speedup 1.0000x reference)
#include <cuda_runtime.h>
#include <math.h>

// Problem constants (fixed by the reference):
//   x  : [E=8, M=2048, D=1024]  fp32
//   w1 : [E, D=1024, H=4096]    fp32
//   w2 : [E, H=4096, D=1024]    fp32
//   out: [E, M, D]              fp32
// out = gelu_exact(x @ w1) @ w2   per expert.

static constexpr int E = 8;
static constexpr int M = 2048;
static constexpr int D = 1024;
static constexpr int H = 4096;

// Scratch for the intermediate activation (256 MB). Device global => no runtime
// allocation, harness-legal.
__device__ float g_hidden[(size_t)E * M * H];

__device__ __forceinline__ float gelu_exact(float x) {
    // matches jax.nn.gelu(approximate=False): 0.5*x*(1+erf(x/sqrt(2)))
    return 0.5f * x * (1.0f + erff(x * 0.7071067811865476f));
}

// Classic 128x128x16 SGEMM, 256 threads, 8x8 per-thread micro-tile.
// A: [Mdim, Kdim] row-major, B: [Kdim, Ndim] row-major, C: [Mdim, Ndim].
// blockIdx.z = expert. A/C may be redirected to the g_hidden scratch.
template <bool DO_GELU, bool A_IS_HIDDEN, bool C_IS_HIDDEN>
__global__ __launch_bounds__(256, 2)
void sgemm_kernel(const float* __restrict__ Ag,
                  const float* __restrict__ Bg,
                  float* __restrict__ Cg,
                  int Mdim, int Ndim, int Kdim)
{
    constexpr int BM = 128, BN = 128, BK = 16;

    const int e = blockIdx.z;
    const float* A = (A_IS_HIDDEN ? (const float*)g_hidden : Ag) + (size_t)e * Mdim * Kdim;
    const float* B = Bg + (size_t)e * Kdim * Ndim;
    float*       C = (C_IS_HIDDEN ? (float*)g_hidden : Cg) + (size_t)e * Mdim * Ndim;

    __shared__ float As[BK][BM];   // stored transposed: As[k][m]
    __shared__ float Bs[BK][BN];

    const int tid  = threadIdx.x;
    const int brow = blockIdx.y * BM;
    const int bcol = blockIdx.x * BN;

    const int tx = tid & 15;   // 16 thread-cols * 8 = 128
    const int ty = tid >> 4;   // 16 thread-rows * 8 = 128

    float acc[8][8];
    #pragma unroll
    for (int i = 0; i < 8; i++)
        #pragma unroll
        for (int j = 0; j < 8; j++) acc[i][j] = 0.0f;

    // A tile 128x16: 2048 floats = 512 float4; 256 threads x 2
    const int a_row0 = tid >> 2;          // 0..63
    const int a_col  = (tid & 3) * 4;     // 0,4,8,12
    // B tile 16x128: 512 float4; 256 threads x 2
    const int b_row0 = tid >> 5;          // 0..7
    const int b_col  = (tid & 31) * 4;    // 0..124

    for (int k0 = 0; k0 < Kdim; k0 += BK) {
        #pragma unroll
        for (int r = 0; r < 2; r++) {
            const int ar = a_row0 + r * 64;
            float4 av = *reinterpret_cast<const float4*>(
                &A[(size_t)(brow + ar) * Kdim + (k0 + a_col)]);
            As[a_col + 0][ar] = av.x;
            As[a_col + 1][ar] = av.y;
            As[a_col + 2][ar] = av.z;
            As[a_col + 3][ar] = av.w;

            const int brr = b_row0 + r * 8;
            *reinterpret_cast<float4*>(&Bs[brr][b_col]) =
                *reinterpret_cast<const float4*>(
                    &B[(size_t)(k0 + brr) * Ndim + (bcol + b_col)]);
        }
        __syncthreads();

        #pragma unroll
        for (int kk = 0; kk < BK; kk++) {
            float arow[8], brow_r[8];
            #pragma unroll
            for (int i = 0; i < 8; i += 4)
                *reinterpret_cast<float4*>(&arow[i]) =
                    *reinterpret_cast<const float4*>(&As[kk][ty * 8 + i]);
            #pragma unroll
            for (int j = 0; j < 8; j += 4)
                *reinterpret_cast<float4*>(&brow_r[j]) =
                    *reinterpret_cast<const float4*>(&Bs[kk][tx * 8 + j]);
            #pragma unroll
            for (int i = 0; i < 8; i++)
                #pragma unroll
                for (int j = 0; j < 8; j++)
                    acc[i][j] = fmaf(arow[i], brow_r[j], acc[i][j]);
        }
        __syncthreads();
    }

    #pragma unroll
    for (int i = 0; i < 8; i++) {
        const size_t row = (size_t)(brow + ty * 8 + i);
        #pragma unroll
        for (int j = 0; j < 8; j += 4) {
            float4 v;
            v.x = acc[i][j + 0];
            v.y = acc[i][j + 1];
            v.z = acc[i][j + 2];
            v.w = acc[i][j + 3];
            if (DO_GELU) {
                v.x = gelu_exact(v.x);
                v.y = gelu_exact(v.y);
                v.z = gelu_exact(v.z);
                v.w = gelu_exact(v.w);
            }
            *reinterpret_cast<float4*>(&C[row * Ndim + bcol + tx * 8 + j]) = v;
        }
    }
}

extern "C" void kernel_launch(void* const* d_in, const int* in_sizes, int n_in,
                              void* d_out, int out_size) {
    const float* x  = (const float*)d_in[0];   // [E, M, D]
    const float* w1 = (const float*)d_in[1];   // [E, D, H]
    const float* w2 = (const float*)d_in[2];   // [E, H, D]
    float* out = (float*)d_out;                // [E, M, D]
    (void)in_sizes; (void)n_in; (void)out_size;

    dim3 block(256);

    // GEMM1 + GELU: [M,D] @ [D,H] -> hidden [M,H]
    {
        dim3 grid(H / 128, M / 128, E);
        sgemm_kernel<true, false, true><<<grid, block>>>(x, w1, nullptr, M, H, D);
    }
    // GEMM2: hidden [M,H] @ [H,D] -> out [M,D]
    {
        dim3 grid(D / 128, M / 128, E);
        sgemm_kernel<false, true, false><<<grid, block>>>(nullptr, w2, out, M, D, H);
    }
}

// round 5
// speedup vs baseline: 2.6514x; 2.6514x over previous
#include <cuda_runtime.h>
#include <cuda_bf16.h>
#include <cstdint>
#include <math.h>

// out = gelu_exact(x @ w1) @ w2 per expert.
// Split-bf16 scheme on HMMA (mma.sync m16n8k16 bf16):
//   C = Ah*Bh + Al*Bh + Ah*Bl   (drop Al*Bl, ~2^-18 relative)

static constexpr int E = 8;
static constexpr int M = 2048;
static constexpr int D = 1024;
static constexpr int H = 4096;

// ---- device scratch (no runtime allocation allowed) ----
__device__ __align__(256) __nv_bfloat16 g_xh[(size_t)E * M * D];
__device__ __align__(256) __nv_bfloat16 g_xl[(size_t)E * M * D];
__device__ __align__(256) __nv_bfloat16 g_w1h[(size_t)E * H * D];  // [E][H][D] (transposed, K-major)
__device__ __align__(256) __nv_bfloat16 g_w1l[(size_t)E * H * D];
__device__ __align__(256) __nv_bfloat16 g_w2h[(size_t)E * D * H];  // [E][D][H] (transposed, K-major)
__device__ __align__(256) __nv_bfloat16 g_w2l[(size_t)E * D * H];
__device__ __align__(256) __nv_bfloat16 g_hh[(size_t)E * M * H];   // hidden hi [E][M][H]
__device__ __align__(256) __nv_bfloat16 g_hl[(size_t)E * M * H];   // hidden lo

// ======================= helpers =======================
__device__ __forceinline__ uint32_t smem_u32(const void* p) {
    uint32_t a;
    asm("{ .reg .u64 t; cvta.to.shared.u64 t, %1; cvt.u32.u64 %0, t; }" : "=r"(a) : "l"(p));
    return a;
}
__device__ __forceinline__ void cp16(uint32_t dst, const void* src) {
    asm volatile("cp.async.cg.shared.global [%0], [%1], 16;" :: "r"(dst), "l"(src));
}
#define CP_COMMIT() asm volatile("cp.async.commit_group;" ::: "memory")

__device__ __forceinline__ void ldsm_x4(uint32_t& r0, uint32_t& r1, uint32_t& r2,
                                        uint32_t& r3, uint32_t addr) {
    asm volatile("ldmatrix.sync.aligned.m8n8.x4.shared.b16 {%0,%1,%2,%3}, [%4];"
                 : "=r"(r0), "=r"(r1), "=r"(r2), "=r"(r3) : "r"(addr));
}
__device__ __forceinline__ void mma_bf16(float& d0, float& d1, float& d2, float& d3,
                                         uint32_t a0, uint32_t a1, uint32_t a2, uint32_t a3,
                                         uint32_t b0, uint32_t b1) {
    asm volatile(
        "mma.sync.aligned.m16n8k16.row.col.f32.bf16.bf16.f32 "
        "{%0,%1,%2,%3}, {%4,%5,%6,%7}, {%8,%9}, {%0,%1,%2,%3};"
        : "+f"(d0), "+f"(d1), "+f"(d2), "+f"(d3)
        : "r"(a0), "r"(a1), "r"(a2), "r"(a3), "r"(b0), "r"(b1));
}

__device__ __forceinline__ float gelu_exact(float x) {
    return 0.5f * x * (1.0f + erff(x * 0.7071067811865476f));
}

// ======================= conversion kernels =======================
__global__ void split_kernel(const float4* __restrict__ in,
                             __nv_bfloat16* __restrict__ hi,
                             __nv_bfloat16* __restrict__ lo) {
    size_t i = (size_t)blockIdx.x * blockDim.x + threadIdx.x;
    float4 v = in[i];
    float f[4] = {v.x, v.y, v.z, v.w};
    __nv_bfloat16 h[4], l[4];
#pragma unroll
    for (int j = 0; j < 4; j++) {
        h[j] = __float2bfloat16(f[j]);
        l[j] = __float2bfloat16(f[j] - __bfloat162float(h[j]));
    }
    *reinterpret_cast<uint2*>(hi + i * 4) = *reinterpret_cast<uint2*>(h);
    *reinterpret_cast<uint2*>(lo + i * 4) = *reinterpret_cast<uint2*>(l);
}

// in [R][C] per expert -> out [C][R] split to hi/lo
__global__ void transpose_split_kernel(const float* __restrict__ in,
                                       __nv_bfloat16* __restrict__ oh,
                                       __nv_bfloat16* __restrict__ ol,
                                       int R, int C) {
    __shared__ float tile[32][33];
    const float* src = in + (size_t)blockIdx.z * R * C;
    __nv_bfloat16* dh = oh + (size_t)blockIdx.z * R * C;
    __nv_bfloat16* dl = ol + (size_t)blockIdx.z * R * C;
    int c0 = blockIdx.x * 32, r0 = blockIdx.y * 32;
    int tx = threadIdx.x, ty = threadIdx.y;
#pragma unroll
    for (int i = ty; i < 32; i += 8)
        tile[i][tx] = src[(size_t)(r0 + i) * C + c0 + tx];
    __syncthreads();
#pragma unroll
    for (int i = ty; i < 32; i += 8) {
        float v = tile[tx][i];
        __nv_bfloat16 h = __float2bfloat16(v);
        float r = v - __bfloat162float(h);
        size_t o = (size_t)(c0 + i) * R + r0 + tx;
        dh[o] = h;
        dl[o] = __float2bfloat16(r);
    }
}

// ======================= HMMA GEMM =======================
// CTA tile 128x128, BK=32 bf16. 8 warps (2x4), warp tile 64x32.
// SMEM per stage: 4 planes (Ah, Al, Bh, Bl), each 128 rows x 80B (padded; 64B data).
// 80B row stride -> quad slot (5r + c) mod 8 distinct for r=0..7: conflict-free ldmatrix.
static constexpr int BK = 32;
static constexpr int ROWB = 80;                       // padded row stride
static constexpr int PLANE_BYTES = 128 * ROWB;        // 10240
static constexpr int STAGE_BYTES = 4 * PLANE_BYTES;   // 40960
static constexpr int STAGES = 3;
static constexpr int SMEM_BYTES = STAGES * STAGE_BYTES;  // 122880
static constexpr int AH_OFF = 0;
static constexpr int AL_OFF = PLANE_BYTES;
static constexpr int BH_OFF = 2 * PLANE_BYTES;
static constexpr int BL_OFF = 3 * PLANE_BYTES;

template <bool GELU_SPLIT>
__global__ __launch_bounds__(256, 1)
void hmma_gemm_kernel(const __nv_bfloat16* __restrict__ Ah,
                      const __nv_bfloat16* __restrict__ Al,
                      const __nv_bfloat16* __restrict__ Bh,
                      const __nv_bfloat16* __restrict__ Bl,
                      float* __restrict__ Cout,
                      __nv_bfloat16* __restrict__ Ch,
                      __nv_bfloat16* __restrict__ Cl,
                      int Mdim, int Ndim, int Kdim) {
    extern __shared__ char smem[];
    const uint32_t sb = smem_u32(smem);

    const int tid = threadIdx.x;
    const int wid = tid >> 5;
    const int lane = tid & 31;
    const int e = blockIdx.z;
    const int brow = blockIdx.y * 128;
    const int bcol = blockIdx.x * 128;

    const size_t mk = (size_t)Mdim * Kdim, nk = (size_t)Ndim * Kdim;
    const size_t mn = (size_t)Mdim * Ndim;
    Ah += (size_t)e * mk; Al += (size_t)e * mk;
    Bh += (size_t)e * nk; Bl += (size_t)e * nk;
    if (GELU_SPLIT) { Ch += (size_t)e * mn; Cl += (size_t)e * mn; }
    else            { Cout += (size_t)e * mn; }

    const int warp_m = (wid >> 2) * 64;   // 0 or 64
    const int warp_n = (wid & 3) * 32;    // 0,32,64,96

    // per-lane ldmatrix row/quad decomposition
    const int lr = lane & 7, lg = lane >> 3;
    const int a_row = lr + (lg & 1) * 8;     // row within 16-row tile
    const int a_q   = lg >> 1;               // k-half
    const int b_row = lr + (lg >> 1) * 8;    // row within 16-n-row pair
    const int b_q   = lg & 1;

    float acc[4][4][4];
#pragma unroll
    for (int i = 0; i < 4; i++)
#pragma unroll
        for (int j = 0; j < 4; j++)
#pragma unroll
            for (int r = 0; r < 4; r++) acc[i][j][r] = 0.0f;

    const int NK = Kdim / BK;

    auto load_stage = [&](int kc, int stage) {
        const int k0 = kc * BK;
        const uint32_t st = sb + stage * STAGE_BYTES;
        // 512 quads (16B) per plane; 256 threads -> 2 per plane
#pragma unroll
        for (int half = 0; half < 2; half++) {
            const int q = tid + half * 256;
            const int r = q >> 2, c = q & 3;
            const uint32_t doff = r * ROWB + c * 16;
            const size_t aoff = (size_t)(brow + r) * Kdim + k0 + c * 8;
            const size_t boff = (size_t)(bcol + r) * Kdim + k0 + c * 8;
            cp16(st + AH_OFF + doff, Ah + aoff);
            cp16(st + AL_OFF + doff, Al + aoff);
            cp16(st + BH_OFF + doff, Bh + boff);
            cp16(st + BL_OFF + doff, Bl + boff);
        }
        CP_COMMIT();
    };

    load_stage(0, 0);
    if (NK > 1) load_stage(1, 1);

    for (int k = 0; k < NK; k++) {
        const int s = k % STAGES;
        const uint32_t st = sb + s * STAGE_BYTES;
        if (k + 1 < NK) asm volatile("cp.async.wait_group 1;" ::: "memory");
        else            asm volatile("cp.async.wait_group 0;" ::: "memory");
        __syncthreads();

#pragma unroll
        for (int ks = 0; ks < 2; ks++) {
            uint32_t ah[4][4], al[4][4], bh[4][2], bl[4][2];
            // A fragments: m-tiles i=0..3 (16 rows each)
            const uint32_t a_base =
                st + (warp_m + a_row) * ROWB + (2 * ks + a_q) * 16;
#pragma unroll
            for (int i = 0; i < 4; i++) {
                ldsm_x4(ah[i][0], ah[i][1], ah[i][2], ah[i][3],
                        a_base + AH_OFF + i * 16 * ROWB);
                ldsm_x4(al[i][0], al[i][1], al[i][2], al[i][3],
                        a_base + AL_OFF + i * 16 * ROWB);
            }
            // B fragments: n-tile pairs jp=0,1 (16 n-rows each)
            const uint32_t b_base =
                st + (warp_n + b_row) * ROWB + (2 * ks + b_q) * 16;
#pragma unroll
            for (int jp = 0; jp < 2; jp++) {
                ldsm_x4(bh[2 * jp][0], bh[2 * jp][1], bh[2 * jp + 1][0], bh[2 * jp + 1][1],
                        b_base + BH_OFF + jp * 16 * ROWB);
                ldsm_x4(bl[2 * jp][0], bl[2 * jp][1], bl[2 * jp + 1][0], bl[2 * jp + 1][1],
                        b_base + BL_OFF + jp * 16 * ROWB);
            }
#pragma unroll
            for (int i = 0; i < 4; i++)
#pragma unroll
                for (int j = 0; j < 4; j++) {
                    mma_bf16(acc[i][j][0], acc[i][j][1], acc[i][j][2], acc[i][j][3],
                             ah[i][0], ah[i][1], ah[i][2], ah[i][3], bh[j][0], bh[j][1]);
                    mma_bf16(acc[i][j][0], acc[i][j][1], acc[i][j][2], acc[i][j][3],
                             al[i][0], al[i][1], al[i][2], al[i][3], bh[j][0], bh[j][1]);
                    mma_bf16(acc[i][j][0], acc[i][j][1], acc[i][j][2], acc[i][j][3],
                             ah[i][0], ah[i][1], ah[i][2], ah[i][3], bl[j][0], bl[j][1]);
                }
        }
        if (k + 2 < NK) load_stage(k + 2, (k + 2) % STAGES);
    }

    // ---- epilogue ----
    const int lrow = lane >> 2;          // 0..7
    const int lcol = (lane & 3) * 2;     // 0,2,4,6
#pragma unroll
    for (int i = 0; i < 4; i++) {
#pragma unroll
        for (int hh = 0; hh < 2; hh++) {
            const size_t row = (size_t)(brow + warp_m + i * 16 + lrow + hh * 8);
#pragma unroll
            for (int j = 0; j < 4; j++) {
                const size_t col = (size_t)(bcol + warp_n + j * 8 + lcol);
                float v0 = acc[i][j][2 * hh];
                float v1 = acc[i][j][2 * hh + 1];
                if (GELU_SPLIT) {
                    v0 = gelu_exact(v0);
                    v1 = gelu_exact(v1);
                    __nv_bfloat16 h0 = __float2bfloat16(v0);
                    __nv_bfloat16 h1 = __float2bfloat16(v1);
                    __nv_bfloat162 hp; hp.x = h0; hp.y = h1;
                    __nv_bfloat162 lp;
                    lp.x = __float2bfloat16(v0 - __bfloat162float(h0));
                    lp.y = __float2bfloat16(v1 - __bfloat162float(h1));
                    *reinterpret_cast<uint32_t*>(Ch + row * Ndim + col) =
                        *reinterpret_cast<uint32_t*>(&hp);
                    *reinterpret_cast<uint32_t*>(Cl + row * Ndim + col) =
                        *reinterpret_cast<uint32_t*>(&lp);
                } else {
                    float2 o; o.x = v0; o.y = v1;
                    *reinterpret_cast<float2*>(Cout + row * Ndim + col) = o;
                }
            }
        }
    }
}

// ======================= launch =======================
extern "C" void kernel_launch(void* const* d_in, const int* in_sizes, int n_in,
                              void* d_out, int out_size) {
    const float* x  = (const float*)d_in[0];
    const float* w1 = (const float*)d_in[1];
    const float* w2 = (const float*)d_in[2];
    float* out = (float*)d_out;
    (void)in_sizes; (void)n_in; (void)out_size;

    cudaFuncSetAttribute(hmma_gemm_kernel<true>,
                         cudaFuncAttributeMaxDynamicSharedMemorySize, SMEM_BYTES);
    cudaFuncSetAttribute(hmma_gemm_kernel<false>,
                         cudaFuncAttributeMaxDynamicSharedMemorySize, SMEM_BYTES);

    __nv_bfloat16 *xh, *xl, *w1h, *w1l, *w2h, *w2l, *hh, *hl;
    cudaGetSymbolAddress((void**)&xh,  g_xh);
    cudaGetSymbolAddress((void**)&xl,  g_xl);
    cudaGetSymbolAddress((void**)&w1h, g_w1h);
    cudaGetSymbolAddress((void**)&w1l, g_w1l);
    cudaGetSymbolAddress((void**)&w2h, g_w2h);
    cudaGetSymbolAddress((void**)&w2l, g_w2l);
    cudaGetSymbolAddress((void**)&hh,  g_hh);
    cudaGetSymbolAddress((void**)&hl,  g_hl);

    // 1) split x
    {
        size_t n4 = (size_t)E * M * D / 4;
        split_kernel<<<(unsigned)(n4 / 256), 256>>>((const float4*)x, xh, xl);
    }
    // 2) transpose+split w1: [E][D][H] -> [E][H][D]
    {
        dim3 grid(H / 32, D / 32, E), blk(32, 8);
        transpose_split_kernel<<<grid, blk>>>(w1, w1h, w1l, D, H);
    }
    // 3) transpose+split w2: [E][H][D] -> [E][D][H]
    {
        dim3 grid(D / 32, H / 32, E), blk(32, 8);
        transpose_split_kernel<<<grid, blk>>>(w2, w2h, w2l, H, D);
    }
    // 4) GEMM1 + GELU + split -> hidden planes  (M x H, K = D)
    {
        dim3 grid(H / 128, M / 128, E);
        hmma_gemm_kernel<true><<<grid, 256, SMEM_BYTES>>>(
            xh, xl, w1h, w1l, nullptr, hh, hl, M, H, D);
    }
    // 5) GEMM2 -> out  (M x D, K = H)
    {
        dim3 grid(D / 128, M / 128, E);
        hmma_gemm_kernel<false><<<grid, 256, SMEM_BYTES>>>(
            hh, hl, w2h, w2l, out, nullptr, nullptr, M, D, H);
    }
}